// round 9
// baseline (speedup 1.0000x reference)
#include <cuda_runtime.h>
#include <cstdint>

// Problem constants (from reference)
#define SEQ    4096
#define CIN    7
#define NK     586        // 585 regular kernels + 1 "last"
#define GLEN   12288      // SEQ * KW(3)
#define HP     12289      // output positions per channel-kernel row
#define GPITCH 12304      // GLEN + 16, keeps 16B alignment
#define CTOT   4096       // 7*585 + 1
#define NCP    2048       // c-pairs
#define HCHUNK 32         // rows per CTA
#define TROWS  8          // rows per smem tile (bulk-copy granularity)

typedef unsigned long long u64;

// Scratch (allocation-free rule: __device__ globals). +64 slack for window overreads.
__device__ u64   g_Gdup[CIN * GPITCH + 64]; // duplicated signal: (g,g) f32x2, g[i]=g_ch[i-4]
__device__ float g_Wmid[NK * 8];            // middle column of each 8x3 kernel (slow path)
__device__ u64   g_WpkT[8 * NCP];           // TRANSPOSED packed weights: [tap][cpair]

__device__ __forceinline__ u64 pk2(float lo, float hi) {
    u64 r; asm("mov.b64 %0, {%1,%2};" : "=l"(r) : "f"(lo), "f"(hi)); return r;
}
__device__ __forceinline__ u64 fma2(u64 a, u64 b, u64 c) {
    u64 d; asm("fma.rn.f32x2 %0, %1, %2, %3;" : "=l"(d) : "l"(a), "l"(b), "l"(c)); return d;
}

// ---- fused prep: mid-column weights, transposed packed weight pairs, duplicated signal ----
__global__ void prep(const float* __restrict__ x, const float* __restrict__ kernels) {
    int idx = blockIdx.x * blockDim.x + threadIdx.x;
    if (idx < NK * 8) {
        int k = idx >> 3, a = idx & 7;
        g_Wmid[idx] = kernels[k * 24 + a * 3 + 1];
    }
    if (idx < 8 * NCP) {
        int a = idx / NCP, cp = idx - a * NCP;
        int c0 = 2 * cp, c1 = c0 + 1;
        int k0 = (c0 == CTOT - 1) ? 585 : (c0 % 585);
        int k1 = (c1 == CTOT - 1) ? 585 : (c1 % 585);
        g_WpkT[idx] = pk2(kernels[k0 * 24 + a * 3 + 1], kernels[k1 * 24 + a * 3 + 1]);
    }
    if (idx < CIN * GPITCH) {
        int ch = idx / GPITCH;
        int i  = idx - ch * GPITCH;
        int t  = i - 4;
        float v = 0.f;
        if (t >= 0 && t < GLEN) {
            int s = t / 3;
            int j = t - s * 3;
            int src = s + j;
            if (src > SEQ - 1) src = SEQ - 1;
            v = x[src * CIN + ch];
        }
        g_Gdup[idx] = pk2(v, v);
    }
}

// ---- main kernel: compute into smem, bulk-copy rows to gmem (no STG on hot path) ----
__global__ void __launch_bounds__(256, 4) conv_main(float* __restrict__ out) {
    const int tid   = threadIdx.x;
    const int cp    = blockIdx.x * 256 + tid;   // [0, 2048), grid.x = 8
    const int c0    = cp * 2;
    const int hbase = blockIdx.y * HCHUNK;

    __shared__ __align__(16) float buf[2][TROWS][512];   // 2 x 16KB

    const int ch0 = c0 / 585;
    const int c1  = c0 + 1;
    const int ch1 = (c1 == CTOT - 1) ? 0 : c1 / 585;
    const bool uniform = (ch0 == ch1);

    // Fast-path state
    u64 W[8];
    u64 P[12];
    const u64* __restrict__ gp = &g_Gdup[ch0 * GPITCH + hbase];
    // Slow-path state (4 of 2048 threads)
    float ws0[8], ws1[8];

    if (uniform) {
#pragma unroll
        for (int a = 0; a < 8; a++) W[a] = g_WpkT[a * NCP + cp];
        ulonglong2 a0 = *(const ulonglong2*)(gp);
        ulonglong2 a1 = *(const ulonglong2*)(gp + 2);
        ulonglong2 a2 = *(const ulonglong2*)(gp + 4);
        ulonglong2 a3 = *(const ulonglong2*)(gp + 6);
        ulonglong2 a4 = *(const ulonglong2*)(gp + 8);
        ulonglong2 a5 = *(const ulonglong2*)(gp + 10);
        P[0] = a0.x; P[1] = a0.y; P[2]  = a1.x; P[3]  = a1.y;
        P[4] = a2.x; P[5] = a2.y; P[6]  = a3.x; P[7]  = a3.y;
        P[8] = a4.x; P[9] = a4.y; P[10] = a5.x; P[11] = a5.y;
    } else {
        int kk0 = (c0 == CTOT - 1) ? 585 : c0 % 585;
        int kk1 = (c1 == CTOT - 1) ? 585 : c1 % 585;
#pragma unroll
        for (int a = 0; a < 8; a++) {
            ws0[a] = g_Wmid[kk0 * 8 + a];
            ws1[a] = g_Wmid[kk1 * 8 + a];
        }
    }

    for (int t = 0; t < HCHUNK / TROWS; t++) {          // 4 tiles of 8 rows
        u64* brow = (u64*)&buf[t & 1][0][0];            // row stride = 256 u64
        if (uniform) {
#pragma unroll
            for (int s = 0; s < 2; s++) {               // 2 substeps of 4 rows
#pragma unroll
                for (int u = 0; u < 4; u++) {
                    u64 acc = 0ull;
#pragma unroll
                    for (int a = 0; a < 8; a++) acc = fma2(P[u + a], W[a], acc);
                    brow[(s * 4 + u) * 256 + tid] = acc;   // STS.64
                }
                if (!(t == 3 && s == 1)) {
                    int off = t * 8 + s * 4;
                    ulonglong2 n0 = *(const ulonglong2*)(gp + off + 12);
                    ulonglong2 n1 = *(const ulonglong2*)(gp + off + 14);
#pragma unroll
                    for (int i = 0; i < 8; i++) P[i] = P[i + 4];
                    P[8] = n0.x; P[9] = n0.y; P[10] = n1.x; P[11] = n1.y;
                }
            }
        } else {
#pragma unroll
            for (int r = 0; r < TROWS; r++) {
                int h = hbase + t * 8 + r;
                const float* ga = (const float*)&g_Gdup[ch0 * GPITCH + h];
                const float* gb = (const float*)&g_Gdup[ch1 * GPITCH + h];
                float s0 = 0.f, s1 = 0.f;
#pragma unroll
                for (int a = 0; a < 8; a++) {
                    s0 = fmaf(ga[2 * a], ws0[a], s0);
                    s1 = fmaf(gb[2 * a], ws1[a], s1);
                }
                buf[t & 1][r][tid * 2]     = s0;
                buf[t & 1][r][tid * 2 + 1] = s1;
            }
        }
        __syncthreads();                                 // all STS visible
        if (tid == 0) {
            asm volatile("fence.proxy.async.shared::cta;" ::: "memory");
            int ht = hbase + t * 8;
#pragma unroll
            for (int r = 0; r < TROWS; r++) {
                int h = ht + r;
                if (h < HP) {
                    const float* dst = out + (size_t)h * CTOT + blockIdx.x * 512;
                    uint32_t src = (uint32_t)__cvta_generic_to_shared(&buf[t & 1][r][0]);
                    asm volatile(
                        "cp.async.bulk.global.shared::cta.bulk_group [%0], [%1], %2;"
                        :: "l"(dst), "r"(src), "r"(2048) : "memory");
                }
            }
            asm volatile("cp.async.bulk.commit_group;" ::: "memory");
            asm volatile("cp.async.bulk.wait_group 1;" ::: "memory");  // prev tile's buf free
        }
        __syncthreads();                                 // buffer-free visible to all
    }
    if (tid == 0)
        asm volatile("cp.async.bulk.wait_group 0;" ::: "memory");      // drain before exit
}

extern "C" void kernel_launch(void* const* d_in, const int* in_sizes, int n_in,
                              void* d_out, int out_size) {
    const float* x       = (const float*)d_in[0];
    const float* kernels = (const float*)d_in[1];
    if (n_in >= 2 && in_sizes[0] == NK * 24) {   // defensive: swapped order
        kernels = (const float*)d_in[0];
        x       = (const float*)d_in[1];
    }
    float* out = (float*)d_out;

    prep<<<(CIN * GPITCH + 255) / 256, 256>>>(x, kernels);

    dim3 grid(NCP / 256, (HP + HCHUNK - 1) / HCHUNK);   // (8, 385)
    conv_main<<<grid, 256>>>(out);
}